// round 11
// baseline (speedup 1.0000x reference)
#include <cuda_runtime.h>
#include <cstdint>

// Fixed dataset geometry: 512x512 grid mesh, batch 32.
#define W 512
#define H 512
#define NV (H * W)
#define FCW (W * 3)            // 1536 float columns per grid row
#define ROWB (FCW * 4)         // 6144 bytes per row
#define NT 384                 // threads per block; each owns 4 float-cols
#define SROWS 32               // rows per block strip
#define STRIPS (H / SROWS)     // 16
#define NSTAGE 6               // SMEM ring stages
#define PITCH (ROWB + 32)      // 16B guard + row + 16B guard

__global__ void zero_out_kernel(float* out) {
    if (threadIdx.x == 0) out[0] = 0.0f;
}

__device__ __forceinline__ uint32_t smem_u32(const void* p) {
    uint32_t a;
    asm("{ .reg .u64 t; cvta.to.shared.u64 t, %1; cvt.u32.u64 %0, t; }"
        : "=r"(a) : "l"(p));
    return a;
}

#define MBAR_INIT(a, c) \
    asm volatile("mbarrier.init.shared.b64 [%0], %1;" :: "r"(a), "r"(c) : "memory")
#define MBAR_EXPECT(a, b) \
    asm volatile("mbarrier.arrive.expect_tx.shared.b64 _, [%0], %1;" :: "r"(a), "r"(b) : "memory")
#define TMA_1D(dst, src, n, mb) \
    asm volatile("cp.async.bulk.shared::cta.global.mbarrier::complete_tx::bytes [%0], [%1], %2, [%3];" \
                 :: "r"(dst), "l"(src), "r"(n), "r"(mb) : "memory")
#define MBAR_WAIT(addr, ph) do {                                              \
    uint32_t _a = (addr), _p = (ph), _done;                                   \
    do {                                                                      \
        asm volatile("{ .reg .pred p;"                                        \
            " mbarrier.try_wait.parity.acquire.cta.shared::cta.b64 p, [%1], %2;" \
            " selp.b32 %0, 1, 0, p; }"                                        \
            : "=r"(_done) : "r"(_a), "r"(_p) : "memory");                     \
    } while (!_done);                                                         \
} while (0)

__global__ __launch_bounds__(NT, 3)
void lap_kernel(const float* __restrict__ verts, float* __restrict__ out, float scale)
{
    __shared__ __align__(128) unsigned char ring[NSTAGE * PITCH];
    __shared__ __align__(8) unsigned long long mbar[NSTAGE];
    __shared__ float wsum[NT / 32];

    const unsigned FULL = 0xFFFFFFFFu;
    int tid  = threadIdx.x;
    int lane = tid & 31;
    int wid  = tid >> 5;

    int bb    = blockIdx.x / STRIPS;
    int strip = blockIdx.x % STRIPS;
    int r0    = strip * SROWS;
    const float* vb = verts + (size_t)bb * NV * 3;

    // ---- init: mbarriers + guard zones ----
    if (tid < NSTAGE) MBAR_INIT(smem_u32(&mbar[tid]), 1);
    if (tid < NSTAGE) {
        float4* g = (float4*)(ring + tid * PITCH);
        *g = make_float4(0.f, 0.f, 0.f, 0.f);
    } else if (tid < 2 * NSTAGE) {
        int s = tid - NSTAGE;
        float4* g = (float4*)(ring + s * PITCH + 16 + ROWB);
        *g = make_float4(0.f, 0.f, 0.f, 0.f);
    }
    __syncthreads();

    uint32_t ringA = smem_u32(ring);
    uint32_t mbarA = smem_u32(mbar);

    // ---- prologue: stage rows r0-1 .. r0+3 into slots 0..4 ----
    if (tid == 0) {
#pragma unroll
        for (int s = 0; s < 5; s++) {
            int row = r0 - 1 + s;
            if (row < 0) row = 0;
            if (row > H - 1) row = H - 1;
            MBAR_EXPECT(mbarA + 8u * s, (uint32_t)ROWB);
            TMA_1D(ringA + s * PITCH + 16, (const void*)(vb + (size_t)row * FCW),
                   (uint32_t)ROWB, mbarA + 8u * s);
        }
    }

    // Per-thread column window: cols 4*tid-4 .. 4*tid+7 (12 floats, bytes 16t..16t+48).
    int f0 = tid * 4;
    bool edgeT = (tid == 0) || (tid == NT - 1);
    float mLc[4], mRc[4];
#pragma unroll
    for (int t = 0; t < 4; t++) {
        mLc[t] = (f0 + t >= 3)       ? 1.0f : 0.0f;
        mRc[t] = (f0 + t <= FCW - 4) ? 1.0f : 0.0f;
    }

    float Aw[12], Bw[12], Cw[12];
    auto load_window = [&](int slot, float w[12]) {
        const float4* p = (const float4*)(ring + slot * PITCH + tid * 16);
        float4 v0 = p[0], v1 = p[1], v2 = p[2];
        w[0] = v0.x; w[1]  = v0.y; w[2]  = v0.z; w[3]  = v0.w;
        w[4] = v1.x; w[5]  = v1.y; w[6]  = v1.z; w[7]  = v1.w;
        w[8] = v2.x; w[9]  = v2.y; w[10] = v2.z; w[11] = v2.w;
    };

    // wait rows r0-1 (slot 0) and r0 (slot 1), load A/B windows
    MBAR_WAIT(mbarA + 0u, 0u);
    MBAR_WAIT(mbarA + 8u, 0u);
    load_window(0, Aw);
    load_window(1, Bw);

    float acc = 0.0f;

#pragma unroll 2
    for (int k = 0; k < SROWS; k++) {
        int i = r0 + k;
        __syncthreads();                           // bounds consumer/producer skew

        if (tid == 0 && k <= SROWS - 4) {          // stage row i+4
            int li  = k + 5;
            int sl  = li % NSTAGE;
            int row = i + 4; if (row > H - 1) row = H - 1;
            MBAR_EXPECT(mbarA + 8u * sl, (uint32_t)ROWB);
            TMA_1D(ringA + sl * PITCH + 16, (const void*)(vb + (size_t)row * FCW),
                   (uint32_t)ROWB, mbarA + 8u * sl);
        }

        // wait row i+1 (C)
        int liC = k + 2;
        MBAR_WAIT(mbarA + 8u * (liC % NSTAGE), (uint32_t)((liC / NSTAGE) & 1));
        load_window(liC % NSTAGE, Cw);

        float mU = (i > 0)     ? 1.0f : 0.0f;
        float mD = (i < H - 1) ? 1.0f : 0.0f;
        float coefI = -__frcp_rn(2.0f + 2.0f * (mU + mD));

        if (edgeT) {
#pragma unroll
            for (int t = 0; t < 4; t++) {
                float sl_ = fmaf(mD, Cw[1 + t], Bw[1 + t]);
                float sr_ = fmaf(mU, Aw[7 + t], Bw[7 + t]);
                float s   = fmaf(mU, Aw[4 + t], mD * Cw[4 + t]);
                s = fmaf(mLc[t], sl_, s);
                s = fmaf(mRc[t], sr_, s);
                float deg = mU + mD + mLc[t] * (1.0f + mD) + mRc[t] * (1.0f + mU);
                float Lv  = fmaf(-__frcp_rn(deg), s, Bw[4 + t]);
                acc = fmaf(Lv, Lv, acc);
            }
        } else {
#pragma unroll
            for (int t = 0; t < 4; t++) {
                float t1 = Bw[1 + t] + Bw[7 + t];
                float t2 = Aw[4 + t] + Aw[7 + t];
                float t3 = Cw[1 + t] + Cw[4 + t];
                float s  = fmaf(mU, t2, t1);
                s = fmaf(mD, t3, s);
                float Lv = fmaf(coefI, s, Bw[4 + t]);
                acc = fmaf(Lv, Lv, acc);
            }
        }

        // rotate windows (register renaming under unroll)
#pragma unroll
        for (int t = 0; t < 12; t++) { Aw[t] = Bw[t]; Bw[t] = Cw[t]; }
    }

    // ---- reduce: warp -> block -> global atomic ----
#pragma unroll
    for (int off = 16; off > 0; off >>= 1)
        acc += __shfl_xor_sync(FULL, acc, off);
    if (lane == 0) wsum[wid] = acc;
    __syncthreads();

    if (wid == 0) {
        float s = (lane < NT / 32) ? wsum[lane] : 0.0f;
#pragma unroll
        for (int off = 8; off > 0; off >>= 1)
            s += __shfl_xor_sync(FULL, s, off);
        if (lane == 0) atomicAdd(out, s * scale);
    }
}

extern "C" void kernel_launch(void* const* d_in, const int* in_sizes, int n_in,
                              void* d_out, int out_size) {
    const float* verts = (const float*)d_in[0];
    int B = in_sizes[0] / (NV * 3);

    float* out = (float*)d_out;
    zero_out_kernel<<<1, 32>>>(out);

    int total_blocks = B * STRIPS;                 // 512
    float scale = 1.0f / ((float)B * (float)NV);
    lap_kernel<<<total_blocks, NT>>>(verts, out, scale);
}

// round 12
// speedup vs baseline: 1.0792x; 1.0792x over previous
#include <cuda_runtime.h>

// Fixed dataset geometry: 512x512 grid mesh, batch 32.
#define W 512
#define H 512
#define NV (H * W)
#define FC (W * 3)          // 1536 float columns per grid row
#define FCG 12              // warp covers 128 float-cols; thread owns 4
#define RPW 32              // rows per warp chunk
#define CHUNKS (H / RPW)    // 16
#define WPB (FCG * CHUNKS)  // warps per batch = 192
#define BLOCK_THREADS 256
#define WARPS_PER_BLOCK (BLOCK_THREADS / 32)

__global__ void zero_out_kernel(float* out) {
    if (threadIdx.x == 0) out[0] = 0.0f;
}

// Walk RPW rows. Each thread reads its 12-float window [f0-4 .. f0+7] directly
// (3 overlapping LDG.128); neighbor taps are window indices — no shuffles.
// EDGE = warp's column group touches the grid's left/right boundary.
template<bool EDGE>
__device__ __forceinline__ float walk(const float* __restrict__ vb,
                                      int f0, int r0)
{
    // Window-load offsets (floats, 16B aligned). Edge threads clamp into the row;
    // the garbage lanes produced by clamping only ever feed mask-zeroed taps.
    int offL = f0 - 4;
    int offR = f0 + 4;
    if (EDGE) {
        if (offL < 0) offL = 0;
        if (offR > FC - 4) offR = FC - 4;
    }

    // Edge-only per-column masks / coefficients (f = f0+t).
    float mL[4], mR[4], cMid[4], cTop[4], cBot[4];
    if (EDGE) {
#pragma unroll
        for (int t = 0; t < 4; t++) {
            int f = f0 + t;
            mL[t] = (f >= 3)     ? 1.0f : 0.0f;
            mR[t] = (f < FC - 3) ? 1.0f : 0.0f;
            cMid[t] = -1.0f / (2.0f + 2.0f * (mL[t] + mR[t]));
            cTop[t] = -1.0f / (1.0f + 2.0f * mL[t] + mR[t]);
            cBot[t] = -1.0f / (1.0f + mL[t] + 2.0f * mR[t]);
        }
    }

    // Rolling windows: A = row i-1, B = row i, C = row i+1. w[k] = col f0-4+k.
    float A[12], Bw[12], Cw[12];
    float acc = 0.0f;

    auto load_win = [&](int r, float w[12]) {
        const float* row = vb + (size_t)r * FC;
        float4 v0 = __ldg((const float4*)(row + offL));
        float4 v1 = __ldg((const float4*)(row + f0));
        float4 v2 = __ldg((const float4*)(row + offR));
        w[0] = v0.x; w[1]  = v0.y; w[2]  = v0.z; w[3]  = v0.w;
        w[4] = v1.x; w[5]  = v1.y; w[6]  = v1.z; w[7]  = v1.w;
        w[8] = v2.x; w[9]  = v2.y; w[10] = v2.z; w[11] = v2.w;
    };

    // phase: 0 = top row (no up-neighbors), 1 = interior, 2 = bottom row.
    auto compute = [&](int phase) {
        float mU = (phase == 0) ? 0.0f : 1.0f;
        float mD = (phase == 2) ? 0.0f : 1.0f;
#pragma unroll
        for (int t = 0; t < 4; t++) {
            float bm = Bw[1 + t], bp = Bw[7 + t];
            float av = A[4 + t],  ap = A[7 + t];
            float cm = Cw[1 + t], cv = Cw[4 + t];
            float bv = Bw[4 + t];
            float Lv;
            if (EDGE) {
                float sl = fmaf(mD, cm, bm);
                float sr = fmaf(mU, ap, bp);
                float s  = fmaf(mU, av, mD * cv);
                s = fmaf(mL[t], sl, s);
                s = fmaf(mR[t], sr, s);
                float coef = (phase == 0) ? cTop[t] : ((phase == 2) ? cBot[t] : cMid[t]);
                Lv = fmaf(coef, s, bv);
            } else {
                float s;
                float coef;
                if (phase == 0) {        // left, right, down, down-left
                    s = (bm + cm) + (bp + cv);
                    coef = -(1.0f / 4.0f);
                } else if (phase == 2) { // left, right, up, up-right
                    s = (bm + bp) + (av + ap);
                    coef = -(1.0f / 4.0f);
                } else {                 // 6 neighbors
                    s = (bm + cm) + ((bp + ap) + (av + cv));
                    coef = -(1.0f / 6.0f);
                }
                Lv = fmaf(coef, s, bv);
            }
            acc = fmaf(Lv, Lv, acc);
        }
    };

    auto rotate = [&]() {
#pragma unroll
        for (int t = 0; t < 12; t++) { A[t] = Bw[t]; Bw[t] = Cw[t]; }
    };

    // ---- preload rows r0-1 (A; clamped, masked out for top chunk) and r0 (B) ----
    {
        int rm = (r0 > 0) ? r0 - 1 : 0;
        load_win(rm, A);
        load_win(r0, Bw);
    }

    int i    = r0;
    int iend = r0 + RPW;

    if (r0 == 0) {                    // peel top boundary row
        load_win(1, Cw);
        compute(0);
        rotate();
        i = 1;
    }

    int mainEnd = (iend == H) ? H - 1 : iend;
#pragma unroll 4
    for (; i < mainEnd; i++) {
        load_win(i + 1, Cw);
        compute(1);
        rotate();
    }

    if (iend == H) {                  // peel bottom boundary row (stale C masked)
        compute(2);
    }

    return acc;
}

__global__ __launch_bounds__(BLOCK_THREADS)
void lap_kernel(const float* __restrict__ verts, float* __restrict__ out, float scale)
{
    const unsigned FULL = 0xFFFFFFFFu;
    int lane = threadIdx.x & 31;
    int gw   = (blockIdx.x * BLOCK_THREADS + threadIdx.x) >> 5;

    int bb  = gw / WPB;
    int rem = gw - bb * WPB;
    int cg  = rem % FCG;
    int rc  = rem / FCG;
    int r0  = rc * RPW;

    const float* vb = verts + (size_t)bb * NV * 3;
    int f0 = cg * 128 + lane * 4;        // first float column owned by this thread
    bool edge = (cg == 0) || (cg == FCG - 1);

    float acc = edge ? walk<true >(vb, f0, r0)
                     : walk<false>(vb, f0, r0);

    // ---- reduce: warp -> block -> global atomic ----
#pragma unroll
    for (int off = 16; off > 0; off >>= 1)
        acc += __shfl_xor_sync(FULL, acc, off);

    __shared__ float warp_sums[WARPS_PER_BLOCK];
    int wid = threadIdx.x >> 5;
    if (lane == 0) warp_sums[wid] = acc;
    __syncthreads();

    if (threadIdx.x == 0) {
        float s = 0.0f;
#pragma unroll
        for (int k = 0; k < WARPS_PER_BLOCK; k++) s += warp_sums[k];
        atomicAdd(out, s * scale);
    }
}

extern "C" void kernel_launch(void* const* d_in, const int* in_sizes, int n_in,
                              void* d_out, int out_size) {
    const float* verts = (const float*)d_in[0];
    int B = in_sizes[0] / (NV * 3);

    float* out = (float*)d_out;
    zero_out_kernel<<<1, 32>>>(out);

    int total_warps  = B * WPB;                         // 6144
    int total_blocks = total_warps / WARPS_PER_BLOCK;   // 768
    float scale = 1.0f / ((float)B * (float)NV);
    lap_kernel<<<total_blocks, BLOCK_THREADS>>>(verts, out, scale);
}

// round 13
// speedup vs baseline: 1.2718x; 1.1785x over previous
#include <cuda_runtime.h>
#include <cstdint>

// Fixed dataset geometry: 512x512 grid mesh, batch 32.
#define W 512
#define H 512
#define NV (H * W)
#define FC (W * 3)          // 1536 float columns per grid row
#define FCG 12              // warp covers 128 float-cols; thread owns 4
#define RPW 32              // rows per warp chunk
#define CHUNKS (H / RPW)    // 16
#define WPB (FCG * CHUNKS)  // warps per batch = 192
#define BLOCK_THREADS 256
#define WARPS_PER_BLOCK (BLOCK_THREADS / 32)
#define SLOTB 576           // bytes per ring slot (544 data + pad)
#define NSLOT 8

__global__ void zero_out_kernel(float* out) {
    if (threadIdx.x == 0) out[0] = 0.0f;
}

__device__ __forceinline__ uint32_t smem_u32(const void* p) {
    uint32_t a;
    asm("{ .reg .u64 t; cvta.to.shared.u64 t, %1; cvt.u32.u64 %0, t; }"
        : "=r"(a) : "l"(p));
    return a;
}

__device__ __forceinline__ void cp16(uint32_t dst, const void* src) {
    asm volatile("cp.async.cg.shared.global [%0], [%1], 16;" :: "r"(dst), "l"(src) : "memory");
}
__device__ __forceinline__ void cp_commit() {
    asm volatile("cp.async.commit_group;" ::: "memory");
}
__device__ __forceinline__ void cp_wait4() {
    asm volatile("cp.async.wait_group 4;" ::: "memory");
}

// Walk RPW rows. Rows stream through a warp-private SMEM ring via cp.async;
// each thread reads its 12-float window [f0-4 .. f0+7] with 3 LDS.128.
// EDGE = warp's column group touches the grid's left/right boundary.
template<bool EDGE>
__device__ __forceinline__ float walk(const float* __restrict__ vb,
                                      uint32_t ringW, int cg, int lane, int r0)
{
    int base = cg * 128;                 // warp's first float column
    int f0   = base + lane * 4;          // thread's first float column

    // Global source columns (16B aligned). Clamped for boundary warps; the
    // resulting garbage taps are zeroed by mL/mR masks.
    int colMain = base + lane * 4;
    int colHL   = (cg > 0)       ? base - 4   : 0;
    int colHR   = (cg < FCG - 1) ? base + 128 : FC - 4;

    // Edge-only per-column masks / coefficients (f = f0+t).
    float mL[4], mR[4], cMid[4], cTop[4], cBot[4];
    if (EDGE) {
#pragma unroll
        for (int t = 0; t < 4; t++) {
            int f = f0 + t;
            mL[t] = (f >= 3)     ? 1.0f : 0.0f;
            mR[t] = (f < FC - 3) ? 1.0f : 0.0f;
            cMid[t] = -1.0f / (2.0f + 2.0f * (mL[t] + mR[t]));
            cTop[t] = -1.0f / (1.0f + 2.0f * mL[t] + mR[t]);
            cBot[t] = -1.0f / (1.0f + mL[t] + 2.0f * mR[t]);
        }
    }

    // Issue one row into ring slot s. Slot layout (floats):
    // [0..3] halo-left (cols base-4..base-1), [4..131] main, [132..135] halo-right.
    auto issue_row = [&](int r, int s) {
        if (r > H - 1) r = H - 1;
        const float* row = vb + (size_t)r * FC;
        uint32_t slot = ringW + (uint32_t)(s * SLOTB);
        cp16(slot + 16u + (uint32_t)(lane * 16), row + colMain);
        if (lane == 0)  cp16(slot,        row + colHL);
        if (lane == 31) cp16(slot + 528u, row + colHR);
        cp_commit();
    };

    // Rolling windows: A = row i-1, B = row i, C = row i+1. w[k] = col f0-4+k.
    float A[12], Bw[12], Cw[12];
    float acc = 0.0f;

    auto load_win = [&](int s, float w[12]) {
        const float4* p = (const float4*)((const char*)0 + 0);  // placeholder (unused)
        (void)p;
        uint32_t a = ringW + (uint32_t)(s * SLOTB) + (uint32_t)(lane * 16);
        float4 v0, v1, v2;
        asm volatile("ld.shared.v4.f32 {%0,%1,%2,%3}, [%4];"
                     : "=f"(v0.x), "=f"(v0.y), "=f"(v0.z), "=f"(v0.w) : "r"(a));
        asm volatile("ld.shared.v4.f32 {%0,%1,%2,%3}, [%4];"
                     : "=f"(v1.x), "=f"(v1.y), "=f"(v1.z), "=f"(v1.w) : "r"(a + 16u));
        asm volatile("ld.shared.v4.f32 {%0,%1,%2,%3}, [%4];"
                     : "=f"(v2.x), "=f"(v2.y), "=f"(v2.z), "=f"(v2.w) : "r"(a + 32u));
        w[0] = v0.x; w[1]  = v0.y; w[2]  = v0.z; w[3]  = v0.w;
        w[4] = v1.x; w[5]  = v1.y; w[6]  = v1.z; w[7]  = v1.w;
        w[8] = v2.x; w[9]  = v2.y; w[10] = v2.z; w[11] = v2.w;
    };

    // phase: 0 = top row (no up-neighbors), 1 = interior, 2 = bottom row.
    auto compute = [&](int phase) {
        float mU = (phase == 0) ? 0.0f : 1.0f;
        float mD = (phase == 2) ? 0.0f : 1.0f;
#pragma unroll
        for (int t = 0; t < 4; t++) {
            float bm = Bw[1 + t], bp = Bw[7 + t];
            float av = A[4 + t],  ap = A[7 + t];
            float cm = Cw[1 + t], cv = Cw[4 + t];
            float bv = Bw[4 + t];
            float Lv;
            if (EDGE) {
                float sl = fmaf(mD, cm, bm);
                float sr = fmaf(mU, ap, bp);
                float s  = fmaf(mU, av, mD * cv);
                s = fmaf(mL[t], sl, s);
                s = fmaf(mR[t], sr, s);
                float coef = (phase == 0) ? cTop[t] : ((phase == 2) ? cBot[t] : cMid[t]);
                Lv = fmaf(coef, s, bv);
            } else {
                float s, coef;
                if (phase == 0) {        // left, right, down, down-left
                    s = (bm + cm) + (bp + cv);
                    coef = -(1.0f / 4.0f);
                } else if (phase == 2) { // left, right, up, up-right
                    s = (bm + bp) + (av + ap);
                    coef = -(1.0f / 4.0f);
                } else {                 // 6 neighbors
                    s = (bm + cm) + ((bp + ap) + (av + cv));
                    coef = -(1.0f / 6.0f);
                }
                Lv = fmaf(coef, s, bv);
            }
            acc = fmaf(Lv, Lv, acc);
        }
    };

    auto rotate = [&]() {
#pragma unroll
        for (int t = 0; t < 12; t++) { A[t] = Bw[t]; Bw[t] = Cw[t]; }
    };

    // ---- prologue: issue rows r0-1 .. r0+4 into slots 0..5 ----
#pragma unroll
    for (int s = 0; s < 6; s++) {
        int r = r0 - 1 + s;
        if (r < 0) r = 0;
        issue_row(r, s);
    }
    cp_wait4();                        // rows r0-1, r0 complete
    __syncwarp();
    load_win(0, A);                    // row r0-1 (clamped; masked for top chunk)
    load_win(1, Bw);                   // row r0

    // One pipeline step: i = r0+k. Issues row i+5, waits row i+1, computes row i.
    auto step = [&](int k, int phase) {
        issue_row(r0 + k + 5, (k + 6) & (NSLOT - 1));
        cp_wait4();                    // row i+1 (slot k+2) complete
        __syncwarp();
        load_win((k + 2) & (NSLOT - 1), Cw);
        compute(phase);
        rotate();
    };

    int k = 0;
    if (r0 == 0) { step(0, 0); k = 1; }          // peel top boundary row
    bool hasBot = (r0 + RPW == H);
    int kmain = hasBot ? RPW - 1 : RPW;
#pragma unroll 4
    for (; k < kmain; k++) step(k, 1);
    if (hasBot) step(RPW - 1, 2);                // peel bottom row (C masked)

    return acc;
}

__global__ __launch_bounds__(BLOCK_THREADS, 3)
void lap_kernel(const float* __restrict__ verts, float* __restrict__ out, float scale)
{
    __shared__ __align__(128) unsigned char ring[WARPS_PER_BLOCK * NSLOT * SLOTB];
    __shared__ float warp_sums[WARPS_PER_BLOCK];

    const unsigned FULL = 0xFFFFFFFFu;
    int lane = threadIdx.x & 31;
    int wid  = threadIdx.x >> 5;
    int gw   = (blockIdx.x * BLOCK_THREADS + threadIdx.x) >> 5;

    int bb  = gw / WPB;
    int rem = gw - bb * WPB;
    int cg  = rem % FCG;
    int rc  = rem / FCG;
    int r0  = rc * RPW;

    const float* vb = verts + (size_t)bb * NV * 3;
    uint32_t ringW = smem_u32(ring) + (uint32_t)(wid * NSLOT * SLOTB);
    bool edge = (cg == 0) || (cg == FCG - 1);

    float acc = edge ? walk<true >(vb, ringW, cg, lane, r0)
                     : walk<false>(vb, ringW, cg, lane, r0);

    // drain any outstanding async copies before SMEM reuse / exit
    asm volatile("cp.async.wait_all;" ::: "memory");
    __syncwarp();

    // ---- reduce: warp -> block -> global atomic ----
#pragma unroll
    for (int off = 16; off > 0; off >>= 1)
        acc += __shfl_xor_sync(FULL, acc, off);

    if (lane == 0) warp_sums[wid] = acc;
    __syncthreads();

    if (threadIdx.x == 0) {
        float s = 0.0f;
#pragma unroll
        for (int k = 0; k < WARPS_PER_BLOCK; k++) s += warp_sums[k];
        atomicAdd(out, s * scale);
    }
}

extern "C" void kernel_launch(void* const* d_in, const int* in_sizes, int n_in,
                              void* d_out, int out_size) {
    const float* verts = (const float*)d_in[0];
    int B = in_sizes[0] / (NV * 3);

    float* out = (float*)d_out;
    zero_out_kernel<<<1, 32>>>(out);

    int total_warps  = B * WPB;                         // 6144
    int total_blocks = total_warps / WARPS_PER_BLOCK;   // 768
    float scale = 1.0f / ((float)B * (float)NV);
    lap_kernel<<<total_blocks, BLOCK_THREADS>>>(verts, out, scale);
}